// round 7
// baseline (speedup 1.0000x reference)
#include <cuda_runtime.h>

#define IMG     512
#define TX      32
#define TY      32
#define KW      11
#define RAD     5
#define HTILE   (TY + KW - 1)   /* 42 */
#define WTILE   (TX + KW - 1)   /* 42 */
#define WPAD    44              /* padded smem row stride in float2 */
#define GX      (IMG / TX)      /* 16 */
#define GY      (IMG / TY)      /* 16 */
#define NPLANES 48
#define NBLK    (GX * GY * NPLANES)  /* 12288 */
#define NPIXD   12582912.0           /* 16*3*512*512 */

// Gaussian window (sigma=1.5, K=11), normalized. Literals -> FFMA-imm (rt=1).
#define G0  1.0283800e-03f
#define G1  7.5988187e-03f
#define G2  3.6000773e-02f
#define G3  1.0936069e-01f
#define G4  2.1300553e-01f
#define G5  2.6601131e-01f
#define G6  G4
#define G7  G3
#define G8  G2
#define G9  G1
#define G10 G0

// Select tap literal by compile-time constant k (folds after full unroll).
#define GWc(k) ((k) == 0 ? G0 : (k) == 1 ? G1 : (k) == 2 ? G2 : (k) == 3 ? G3 : \
                (k) == 4 ? G4 : (k) == 5 ? G5 : (k) == 6 ? G6 : (k) == 7 ? G7 : \
                (k) == 8 ? G8 : (k) == 9 ? G9 : G10)

__device__ float g_part[NBLK];
__device__ int   g_count = 0;

__global__ __launch_bounds__(256, 6) void ssim_main(const float* __restrict__ x,
                                                    const float* __restrict__ y,
                                                    float* __restrict__ out) {
    // Four fields after horizontal conv, packed: (hx, hy, hz, hw)
    //   z = x^2 + y^2  (conv linearity: conv(x^2)+conv(y^2) = conv(z))
    //   w = x*y
    __shared__ float2 xys[HTILE][WPAD];   // (x, y) input tile     14.8 KB
    __shared__ float4 Hs[HTILE][TX];      // packed H fields       21.0 KB
    __shared__ float  red[8];

    const int tid   = threadIdx.x;
    const int plane = blockIdx.z;
    const int c0    = blockIdx.x * TX;
    const int r0    = blockIdx.y * TY;
    const float* xp = x + (size_t)plane * (IMG * IMG);
    const float* yp = y + (size_t)plane * (IMG * IMG);

    // ---- Phase 0: cooperative halo load (zero-pad at image borders) ----
    for (int i = tid; i < HTILE * WTILE; i += 256) {
        int lr = i / WTILE, lc = i - lr * WTILE;
        int gr = r0 + lr - RAD, gc = c0 + lc - RAD;
        bool ok = (gr >= 0) & (gr < IMG) & (gc >= 0) & (gc < IMG);
        float xv = 0.f, yv = 0.f;
        if (ok) {
            int g = gr * IMG + gc;
            xv = xp[g];
            yv = yp[g];
        }
        xys[lr][lc] = make_float2(xv, yv);
    }
    __syncthreads();

    // ---- Phase 1: horizontal conv, accumulator streaming (low reg) ----
    // 42 rows * 8 chunks = 336 tasks on 256 threads
    for (int t = tid; t < HTILE * (TX / 4); t += 256) {
        int lr  = t >> 3;
        int cc4 = (t & 7) << 2;

        float ax[4] = {0.f, 0.f, 0.f, 0.f};
        float ay[4] = {0.f, 0.f, 0.f, 0.f};
        float az[4] = {0.f, 0.f, 0.f, 0.f};
        float aw[4] = {0.f, 0.f, 0.f, 0.f};
#pragma unroll
        for (int j = 0; j < 14; j++) {
            float2 v = xys[lr][cc4 + j];
            float z = fmaf(v.x, v.x, v.y * v.y);
            float w = v.x * v.y;
#pragma unroll
            for (int i = 0; i < 4; i++) {
                if (j >= i && j <= i + 10) {
                    ax[i] = fmaf(GWc(j - i), v.x, ax[i]);
                    ay[i] = fmaf(GWc(j - i), v.y, ay[i]);
                    az[i] = fmaf(GWc(j - i), z,   az[i]);
                    aw[i] = fmaf(GWc(j - i), w,   aw[i]);
                }
            }
        }
#pragma unroll
        for (int i = 0; i < 4; i++)
            Hs[lr][cc4 + i] = make_float4(ax[i], ay[i], az[i], aw[i]);
    }
    __syncthreads();

    // ---- Phase 2: vertical conv + SSIM, accumulator streaming ----
    const int lane = tid & 31;          // output column
    const int wrow = (tid >> 5) << 2;   // warp w -> output rows 4w..4w+3
    const float C1 = 0.0001f, C2 = 0.0009f;

    float m1[4] = {0.f, 0.f, 0.f, 0.f};
    float m2[4] = {0.f, 0.f, 0.f, 0.f};
    float cz[4] = {0.f, 0.f, 0.f, 0.f};
    float cw[4] = {0.f, 0.f, 0.f, 0.f};
#pragma unroll
    for (int j = 0; j < 14; j++) {
        float4 v = Hs[wrow + j][lane];
#pragma unroll
        for (int i = 0; i < 4; i++) {
            if (j >= i && j <= i + 10) {
                m1[i] = fmaf(GWc(j - i), v.x, m1[i]);
                m2[i] = fmaf(GWc(j - i), v.y, m2[i]);
                cz[i] = fmaf(GWc(j - i), v.z, cz[i]);
                cw[i] = fmaf(GWc(j - i), v.w, cw[i]);
            }
        }
    }

    float local = 0.f;
#pragma unroll
    for (int i = 0; i < 4; i++) {
        float A = m1[i] * m2[i];                    // mu1*mu2
        float B = fmaf(m1[i], m1[i], m2[i] * m2[i]); // mu1^2 + mu2^2
        float num = (2.f * A + C1) * (2.f * (cw[i] - A) + C2);
        float den = (B + C1) * ((cz[i] - B) + C2);
        local += __fdividef(num, den);
    }

    // ---- block reduction ----
#pragma unroll
    for (int o = 16; o; o >>= 1) local += __shfl_down_sync(0xffffffffu, local, o);
    if (lane == 0) red[tid >> 5] = local;
    __syncthreads();

    __shared__ bool amLast;
    if (tid == 0) {
        float s = 0.f;
#pragma unroll
        for (int w = 0; w < 8; w++) s += red[w];
        int bidx = (blockIdx.z * GY + blockIdx.y) * GX + blockIdx.x;
        g_part[bidx] = s;
        __threadfence();
        int prev = atomicAdd(&g_count, 1);
        amLast = (prev == NBLK - 1);
    }
    __syncthreads();

    // ---- last block: deterministic final reduction (fixed-order reads) ----
    if (amLast) {
        __threadfence();
        double s = 0.0;
        for (int i = tid; i < NBLK; i += 256) s += (double)g_part[i];
#pragma unroll
        for (int o = 16; o; o >>= 1) s += __shfl_down_sync(0xffffffffu, s, o);
        __shared__ double dred[8];
        if (lane == 0) dred[tid >> 5] = s;
        __syncthreads();
        if (tid == 0) {
            double tot = 0.0;
#pragma unroll
            for (int w = 0; w < 8; w++) tot += dred[w];
            out[0] = (float)(1.0 - tot / NPIXD);
            g_count = 0;   // reset for next graph replay
        }
    }
}

extern "C" void kernel_launch(void* const* d_in, const int* in_sizes, int n_in,
                              void* d_out, int out_size) {
    const float* pred  = (const float*)d_in[0];
    const float* label = (const float*)d_in[1];
    float* out = (float*)d_out;

    dim3 grid(GX, GY, NPLANES);   // 16 x 16 x 48
    ssim_main<<<grid, 256>>>(pred, label, out);
}

// round 8
// speedup vs baseline: 1.1920x; 1.1920x over previous
#include <cuda_runtime.h>

#define IMG     512
#define TX      32
#define TY      32
#define KW      11
#define RAD     5
#define HTILE   (TY + KW - 1)   /* 42 */
#define WTILE   (TX + KW - 1)   /* 42 */
#define WPAD    46   /* float2 row stride: 368B = 16 mod 32 -> rows alternate bank phase */
#define HPAD    34   /* float2 row stride: 272B = 16 mod 32 -> rows alternate bank phase */
#define GX      (IMG / TX)      /* 16 */
#define GY      (IMG / TY)      /* 16 */
#define NPLANES 48
#define NBLK    (GX * GY * NPLANES)  /* 12288 */
#define NPIXD   12582912.0           /* 16*3*512*512 */

// Gaussian window (sigma=1.5, K=11), normalized. Literals -> FFMA-imm (rt=1).
#define G0  1.0283800e-03f
#define G1  7.5988187e-03f
#define G2  3.6000773e-02f
#define G3  1.0936069e-01f
#define G4  2.1300553e-01f
#define G5  2.6601131e-01f
#define G6  G4
#define G7  G3
#define G8  G2
#define G9  G1
#define G10 G0

// 11-tap conv over expression E(j), j = i..i+10 (immediate multipliers).
#define CONV11E(E, i)                                                  \
    fmaf(G10, E((i) + 10),                                             \
    fmaf(G9,  E((i) + 9),                                              \
    fmaf(G8,  E((i) + 8),                                              \
    fmaf(G7,  E((i) + 7),                                              \
    fmaf(G6,  E((i) + 6),                                              \
    fmaf(G5,  E((i) + 5),                                              \
    fmaf(G4,  E((i) + 4),                                              \
    fmaf(G3,  E((i) + 3),                                              \
    fmaf(G2,  E((i) + 2),                                              \
    fmaf(G1,  E((i) + 1),                                               \
    G0 * E((i) + 0)))))))))))

__device__ float g_part[NBLK];
__device__ int   g_count = 0;

__global__ __launch_bounds__(256, 4) void ssim_main(const float* __restrict__ x,
                                                    const float* __restrict__ y,
                                                    float* __restrict__ out) {
    // Fields after horizontal conv: (hx, hy) and (hz, hw), where
    //   z = x^2 + y^2  (conv linearity: conv(x^2)+conv(y^2) = conv(z)),  w = x*y
    __shared__ float2 xys[HTILE][WPAD];        // (x, y) input tile    15.5 KB
    __shared__ float2 Hs01[HTILE][HPAD];       // (hx, hy)             11.4 KB
    __shared__ float2 Hszw[HTILE][HPAD];       // (hz, hw)             11.4 KB
    __shared__ float  red[8];

    const int tid   = threadIdx.x;
    const int plane = blockIdx.z;
    const int c0    = blockIdx.x * TX;
    const int r0    = blockIdx.y * TY;
    const float* xp = x + (size_t)plane * (IMG * IMG);
    const float* yp = y + (size_t)plane * (IMG * IMG);

    // ---- Phase 0: cooperative halo load (zero-pad at image borders) ----
    for (int i = tid; i < HTILE * WTILE; i += 256) {
        int lr = i / WTILE, lc = i - lr * WTILE;
        int gr = r0 + lr - RAD, gc = c0 + lc - RAD;
        bool ok = (gr >= 0) & (gr < IMG) & (gc >= 0) & (gc < IMG);
        float xv = 0.f, yv = 0.f;
        if (ok) {
            int g = gr * IMG + gc;
            xv = xp[g];
            yv = yp[g];
        }
        xys[lr][lc] = make_float2(xv, yv);
    }
    __syncthreads();

    // ---- Phase 1: horizontal conv of 4 fields, 4-column chunks ----
    // 42 rows * 8 chunks = 336 tasks on 256 threads
    for (int t = tid; t < HTILE * (TX / 4); t += 256) {
        int lr  = t >> 3;
        int cc4 = (t & 7) << 2;

        float2 v[14];             // (x, y); 7 x LDS.128
#pragma unroll
        for (int q = 0; q < 7; q++)
            *(float4*)&v[q * 2] = *(const float4*)&xys[lr][cc4 + q * 2];

#define EX(j) v[j].x
#define EY(j) v[j].y
        float2 h[4];
#pragma unroll
        for (int cc = 0; cc < 4; cc++) {
            h[cc].x = CONV11E(EX, cc);
            h[cc].y = CONV11E(EY, cc);
        }
        *(float4*)&Hs01[lr][cc4 + 0] = *(float4*)&h[0];
        *(float4*)&Hs01[lr][cc4 + 2] = *(float4*)&h[2];

        // in-place: v[j] := (x^2 + y^2, x*y)
#pragma unroll
        for (int j = 0; j < 14; j++) {
            float a = v[j].x, b = v[j].y;
            v[j].x = fmaf(a, a, b * b);
            v[j].y = a * b;
        }
#pragma unroll
        for (int cc = 0; cc < 4; cc++) {
            h[cc].x = CONV11E(EX, cc);
            h[cc].y = CONV11E(EY, cc);
        }
        *(float4*)&Hszw[lr][cc4 + 0] = *(float4*)&h[0];
        *(float4*)&Hszw[lr][cc4 + 2] = *(float4*)&h[2];
#undef EX
#undef EY
    }
    __syncthreads();

    // ---- Phase 2: vertical conv + SSIM (4-row window per thread) ----
    const int lane = tid & 31;          // output column
    const int wrow = (tid >> 5) << 2;   // warp w -> output rows 4w..4w+3
    const float C1 = 0.0001f, C2 = 0.0009f;

    float A[4], B[4];                   // A = mu1*mu2, B = mu1^2 + mu2^2
    {
        float2 a[14];
#define AX(j) a[j].x
#define AY(j) a[j].y
#pragma unroll
        for (int j = 0; j < 14; j++) a[j] = Hs01[wrow + j][lane];
#pragma unroll
        for (int i = 0; i < 4; i++) {
            float m1 = CONV11E(AX, i);
            float m2 = CONV11E(AY, i);
            A[i] = m1 * m2;
            B[i] = fmaf(m1, m1, m2 * m2);
        }

        float local = 0.f;
#pragma unroll
        for (int j = 0; j < 14; j++) a[j] = Hszw[wrow + j][lane];
#pragma unroll
        for (int i = 0; i < 4; i++) {
            float czz = CONV11E(AX, i);   // conv(x^2)+conv(y^2)
            float cxy = CONV11E(AY, i);   // conv(x*y)
            float num = (2.f * A[i] + C1) * (2.f * (cxy - A[i]) + C2);
            float den = (B[i] + C1) * ((czz - B[i]) + C2);
            local += __fdividef(num, den);
        }
#undef AX
#undef AY

        // ---- block reduction ----
#pragma unroll
        for (int o = 16; o; o >>= 1) local += __shfl_down_sync(0xffffffffu, local, o);
        if (lane == 0) red[tid >> 5] = local;
    }
    __syncthreads();

    __shared__ bool amLast;
    if (tid == 0) {
        float s = 0.f;
#pragma unroll
        for (int w = 0; w < 8; w++) s += red[w];
        int bidx = (blockIdx.z * GY + blockIdx.y) * GX + blockIdx.x;
        g_part[bidx] = s;
        __threadfence();
        int prev = atomicAdd(&g_count, 1);
        amLast = (prev == NBLK - 1);
    }
    __syncthreads();

    // ---- last block: deterministic final reduction (fixed-order reads) ----
    if (amLast) {
        __threadfence();
        double s = 0.0;
        for (int i = tid; i < NBLK; i += 256) s += (double)g_part[i];
#pragma unroll
        for (int o = 16; o; o >>= 1) s += __shfl_down_sync(0xffffffffu, s, o);
        __shared__ double dred[8];
        if (lane == 0) dred[tid >> 5] = s;
        __syncthreads();
        if (tid == 0) {
            double tot = 0.0;
#pragma unroll
            for (int w = 0; w < 8; w++) tot += dred[w];
            out[0] = (float)(1.0 - tot / NPIXD);
            g_count = 0;   // reset for next graph replay
        }
    }
}

extern "C" void kernel_launch(void* const* d_in, const int* in_sizes, int n_in,
                              void* d_out, int out_size) {
    const float* pred  = (const float*)d_in[0];
    const float* label = (const float*)d_in[1];
    float* out = (float*)d_out;

    dim3 grid(GX, GY, NPLANES);   // 16 x 16 x 48
    ssim_main<<<grid, 256>>>(pred, label, out);
}

// round 9
// speedup vs baseline: 1.2805x; 1.0742x over previous
#include <cuda_runtime.h>

#define IMG     512
#define TX      32
#define TY      32
#define KW      11
#define RAD     5
#define HTILE   (TY + KW - 1)   /* 42 */
#define WTILE   (TX + KW - 1)   /* 42 */
#define WPAD    46   /* float2 row stride */
#define HPAD    34   /* float2 row stride */
#define GX      (IMG / TX)      /* 16 */
#define GY      (IMG / TY)      /* 16 */
#define NPLANES 48
#define NBLK    (GX * GY * NPLANES)  /* 12288 */
#define NPIXD   12582912.0           /* 16*3*512*512 */

// Gaussian window (sigma=1.5, K=11), normalized.
#define G0  1.0283800e-03f
#define G1  7.5988187e-03f
#define G2  3.6000773e-02f
#define G3  1.0936069e-01f
#define G4  2.1300553e-01f
#define G5  2.6601131e-01f

typedef unsigned long long u64;

// Packed f32x2 helpers (Blackwell sm_103a). FFMA2 does two independent fp32
// FMAs per instruction -> halves fma-pipe issue slots; bitwise identical to
// two scalar fmaf with the same operand order.
__device__ __forceinline__ u64 pack2(float lo, float hi) {
    u64 r;
    asm("mov.b64 %0, {%1, %2};" : "=l"(r) : "f"(lo), "f"(hi));
    return r;
}
__device__ __forceinline__ void unpack2(u64 v, float& lo, float& hi) {
    asm("mov.b64 {%0, %1}, %2;" : "=f"(lo), "=f"(hi) : "l"(v));
}
#define FMA2(acc, coef, v) \
    asm("fma.rn.f32x2 %0, %1, %2, %0;" : "+l"(acc) : "l"(coef), "l"(v))

// Packed coefficient pair for tap k (symmetric window), compile-time select.
#define GWP(k) ((k)==0||(k)==10 ? GP0 : (k)==1||(k)==9 ? GP1 : \
                (k)==2||(k)==8  ? GP2 : (k)==3||(k)==7 ? GP3 : \
                (k)==4||(k)==6  ? GP4 : GP5)

__device__ float g_part[NBLK];
__device__ int   g_count = 0;

__global__ __launch_bounds__(256) void ssim_main(const float* __restrict__ x,
                                                 const float* __restrict__ y,
                                                 float* __restrict__ out) {
    // Fields after horizontal conv: (hx, hy) and (hz, hw), where
    //   z = x^2 + y^2 (conv linearity),  w = x*y
    __shared__ float2 xys[HTILE][WPAD];        // (x, y) input tile
    __shared__ float2 Hs01[HTILE][HPAD];       // (hx, hy)
    __shared__ float2 Hszw[HTILE][HPAD];       // (hz, hw)
    __shared__ float  red[8];

    const int tid   = threadIdx.x;
    const int plane = blockIdx.z;
    const int c0    = blockIdx.x * TX;
    const int r0    = blockIdx.y * TY;
    const float* xp = x + (size_t)plane * (IMG * IMG);
    const float* yp = y + (size_t)plane * (IMG * IMG);

    // Packed (G,G) coefficient pairs — warp-uniform, built once.
    const u64 GP0 = pack2(G0, G0);
    const u64 GP1 = pack2(G1, G1);
    const u64 GP2 = pack2(G2, G2);
    const u64 GP3 = pack2(G3, G3);
    const u64 GP4 = pack2(G4, G4);
    const u64 GP5 = pack2(G5, G5);

    // ---- Phase 0: cooperative halo load (zero-pad at image borders) ----
    for (int i = tid; i < HTILE * WTILE; i += 256) {
        int lr = i / WTILE, lc = i - lr * WTILE;
        int gr = r0 + lr - RAD, gc = c0 + lc - RAD;
        bool ok = (gr >= 0) & (gr < IMG) & (gc >= 0) & (gc < IMG);
        float xv = 0.f, yv = 0.f;
        if (ok) {
            int g = gr * IMG + gc;
            xv = xp[g];
            yv = yp[g];
        }
        xys[lr][lc] = make_float2(xv, yv);
    }
    __syncthreads();

    // ---- Phase 1: horizontal conv of 4 fields, packed FMA, streaming ----
    // 42 rows * 8 chunks = 336 tasks on 256 threads
    for (int t = tid; t < HTILE * (TX / 4); t += 256) {
        int lr  = t >> 3;
        int cc4 = (t & 7) << 2;

        u64 axy[4] = {0ull, 0ull, 0ull, 0ull};
        u64 azw[4] = {0ull, 0ull, 0ull, 0ull};
#pragma unroll
        for (int j = 0; j < 14; j++) {
            float2 v = xys[lr][cc4 + j];
            u64 vxy = pack2(v.x, v.y);
            float z = fmaf(v.x, v.x, v.y * v.y);
            float w = v.x * v.y;
            u64 vzw = pack2(z, w);
#pragma unroll
            for (int i = 0; i < 4; i++) {
                if (j >= i && j <= i + 10) {
                    FMA2(axy[i], GWP(j - i), vxy);
                    FMA2(azw[i], GWP(j - i), vzw);
                }
            }
        }
#pragma unroll
        for (int i = 0; i < 4; i++) {
            *(u64*)&Hs01[lr][cc4 + i] = axy[i];
            *(u64*)&Hszw[lr][cc4 + i] = azw[i];
        }
    }
    __syncthreads();

    // ---- Phase 2: vertical conv + SSIM, packed FMA, streaming ----
    const int lane = tid & 31;          // output column
    const int wrow = (tid >> 5) << 2;   // warp w -> output rows 4w..4w+3
    const float C1 = 0.0001f, C2 = 0.0009f;

    float A[4], B[4];                   // A = mu1*mu2, B = mu1^2 + mu2^2
    {
        u64 acc[4] = {0ull, 0ull, 0ull, 0ull};
#pragma unroll
        for (int j = 0; j < 14; j++) {
            u64 a = *(const u64*)&Hs01[wrow + j][lane];
#pragma unroll
            for (int i = 0; i < 4; i++)
                if (j >= i && j <= i + 10) FMA2(acc[i], GWP(j - i), a);
        }
#pragma unroll
        for (int i = 0; i < 4; i++) {
            float m1, m2;
            unpack2(acc[i], m1, m2);
            A[i] = m1 * m2;
            B[i] = fmaf(m1, m1, m2 * m2);
        }
    }

    float local = 0.f;
    {
        u64 acc[4] = {0ull, 0ull, 0ull, 0ull};
#pragma unroll
        for (int j = 0; j < 14; j++) {
            u64 a = *(const u64*)&Hszw[wrow + j][lane];
#pragma unroll
            for (int i = 0; i < 4; i++)
                if (j >= i && j <= i + 10) FMA2(acc[i], GWP(j - i), a);
        }
#pragma unroll
        for (int i = 0; i < 4; i++) {
            float czz, cxy;
            unpack2(acc[i], czz, cxy);
            float num = (2.f * A[i] + C1) * (2.f * (cxy - A[i]) + C2);
            float den = (B[i] + C1) * ((czz - B[i]) + C2);
            local += __fdividef(num, den);
        }
    }

    // ---- block reduction ----
#pragma unroll
    for (int o = 16; o; o >>= 1) local += __shfl_down_sync(0xffffffffu, local, o);
    if (lane == 0) red[tid >> 5] = local;
    __syncthreads();

    __shared__ bool amLast;
    if (tid == 0) {
        float s = 0.f;
#pragma unroll
        for (int w = 0; w < 8; w++) s += red[w];
        int bidx = (blockIdx.z * GY + blockIdx.y) * GX + blockIdx.x;
        g_part[bidx] = s;
        __threadfence();
        int prev = atomicAdd(&g_count, 1);
        amLast = (prev == NBLK - 1);
    }
    __syncthreads();

    // ---- last block: deterministic final reduction (fixed-order reads) ----
    if (amLast) {
        __threadfence();
        double s = 0.0;
        for (int i = tid; i < NBLK; i += 256) s += (double)g_part[i];
#pragma unroll
        for (int o = 16; o; o >>= 1) s += __shfl_down_sync(0xffffffffu, s, o);
        __shared__ double dred[8];
        if (lane == 0) dred[tid >> 5] = s;
        __syncthreads();
        if (tid == 0) {
            double tot = 0.0;
#pragma unroll
            for (int w = 0; w < 8; w++) tot += dred[w];
            out[0] = (float)(1.0 - tot / NPIXD);
            g_count = 0;   // reset for next graph replay
        }
    }
}

extern "C" void kernel_launch(void* const* d_in, const int* in_sizes, int n_in,
                              void* d_out, int out_size) {
    const float* pred  = (const float*)d_in[0];
    const float* label = (const float*)d_in[1];
    float* out = (float*)d_out;

    dim3 grid(GX, GY, NPLANES);   // 16 x 16 x 48
    ssim_main<<<grid, 256>>>(pred, label, out);
}